// round 15
// baseline (speedup 1.0000x reference)
#include <cuda_runtime.h>
#include <cuda_fp16.h>
#include <cstdint>

// Shapes fixed by setup_inputs: A [4096,4096] f32, w_q [4096,4096] i32, scales [4096,128] f32
static constexpr int KDIM   = 4096;
static constexpr int NDIM   = 4096;
static constexpr int QBLOCK = 32;

// fp16 scratch: A and dequantized W (32 MB each)
__device__ __half g_Ah[(size_t)4096 * KDIM];
__device__ __half g_Wh[(size_t)NDIM * KDIM];

__device__ __forceinline__ uint32_t smem_u32(const void* p) {
    uint32_t a;
    asm("{ .reg .u64 t; cvta.to.shared.u64 t, %1; cvt.u32.u64 %0, t; }" : "=r"(a) : "l"(p));
    return a;
}

#define SWZ128(off) ((off) ^ (((off) >> 3) & 0x70))

__device__ __forceinline__ void cpa16(uint32_t smem_dst, const void* gmem_src) {
    asm volatile("cp.async.cg.shared.global [%0], [%1], 16;"
                 :: "r"(smem_dst), "l"(gmem_src) : "memory");
}
#define CP_COMMIT() asm volatile("cp.async.commit_group;" ::: "memory")
#define CP_WAIT(n)  asm volatile("cp.async.wait_group %0;" :: "n"(n) : "memory")

#define LDSM4(r0, r1, r2, r3, addr)                                            \
    asm volatile("ldmatrix.sync.aligned.m8n8.x4.shared.b16 {%0,%1,%2,%3}, [%4];" \
                 : "=r"(r0), "=r"(r1), "=r"(r2), "=r"(r3) : "r"(addr))

// fp16-accumulate MMA: D(2 regs) = A(4) * B(2) + C(2)
__device__ __forceinline__ void mma_f16h(uint32_t d[2], const uint32_t a[4],
                                         uint32_t b0, uint32_t b1,
                                         uint32_t c0, uint32_t c1) {
    asm volatile(
        "mma.sync.aligned.m16n8k16.row.col.f16.f16.f16.f16 "
        "{%0,%1}, {%2,%3,%4,%5}, {%6,%7}, {%8,%9};"
        : "=r"(d[0]), "=r"(d[1])
        : "r"(a[0]), "r"(a[1]), "r"(a[2]), "r"(a[3]), "r"(b0), "r"(b1),
          "r"(c0), "r"(c1));
}

// ---------------------------------------------------------------------------
// Kernel 1: fused prep. Blocks [0, 8192): dequant w_q -> fp16 W.
//           Blocks [8192, ...): convert A fp32 -> fp16.
// ---------------------------------------------------------------------------
static constexpr int WQ_BLOCKS = (NDIM * KDIM / 8) / 256;  // 8192

__global__ __launch_bounds__(256) void prep_kernel(const int* __restrict__ wq,
                                                   const float* __restrict__ scales,
                                                   const float* __restrict__ A) {
    if (blockIdx.x < WQ_BLOCKS) {
        int idx  = blockIdx.x * 256 + threadIdx.x;   // 8-elem group
        int base = idx << 3;
        int o    = base >> 12;
        int i    = base & (KDIM - 1);
        float s  = scales[o * (KDIM / QBLOCK) + (i >> 5)];
        const int4* wq4 = reinterpret_cast<const int4*>(wq);
        int4 q0 = wq4[idx * 2];
        int4 q1 = wq4[idx * 2 + 1];
        __half2 h[4];
        h[0] = __floats2half2_rn((float)(q0.x - 128) * s, (float)(q0.y - 128) * s);
        h[1] = __floats2half2_rn((float)(q0.z - 128) * s, (float)(q0.w - 128) * s);
        h[2] = __floats2half2_rn((float)(q1.x - 128) * s, (float)(q1.y - 128) * s);
        h[3] = __floats2half2_rn((float)(q1.z - 128) * s, (float)(q1.w - 128) * s);
        reinterpret_cast<uint4*>(g_Wh)[idx] = *reinterpret_cast<uint4*>(h);
    } else {
        int idx = (blockIdx.x - WQ_BLOCKS) * 256 + threadIdx.x;
        const float4* A4 = reinterpret_cast<const float4*>(A);
        float4 v0 = A4[idx * 2];
        float4 v1 = A4[idx * 2 + 1];
        __half2 h[4];
        h[0] = __floats2half2_rn(v0.x, v0.y);
        h[1] = __floats2half2_rn(v0.z, v0.w);
        h[2] = __floats2half2_rn(v1.x, v1.y);
        h[3] = __floats2half2_rn(v1.z, v1.w);
        reinterpret_cast<uint4*>(g_Ah)[idx] = *reinterpret_cast<uint4*>(h);
    }
}

// ---------------------------------------------------------------------------
// Kernel 2: fp16 GEMM, C = A @ W^T.  CTA 128x128, BK=64, 3-stage cp.async.
// 4 warps as 2(m) x 2(n), warp tile 64x64, 2 CTAs/SM.
// fp16 accumulation within each BK=64 chunk (2x-rate HMMA form), promoted
// into fp32 accumulators once per chunk (64 promotions over K=4096).
// ---------------------------------------------------------------------------
static constexpr int BM = 128, BN = 128, BK = 64, STAGES = 3;
static constexpr int ROWB  = BK * 2;              // 128 bytes per smem row
static constexpr int A_ST  = BM * ROWB;           // 16 KB
static constexpr int ST    = 2 * A_ST;            // A + B per stage: 32 KB
static constexpr int SMEM_BYTES = STAGES * ST;    // 96 KB

__global__ __launch_bounds__(128, 2) void gemm_f16_kernel(float* __restrict__ C, int M) {
    extern __shared__ char smem[];
    const uint32_t sb = smem_u32(smem);

    const int tid  = threadIdx.x;
    const int wid  = tid >> 5;
    const int lane = tid & 31;
    const int grp  = lane >> 2;
    const int tig  = lane & 3;

    const int bm = blockIdx.y * BM;
    const int bn = blockIdx.x * BN;

    const int warp_m = (wid >> 1) * 64;   // 0 / 64
    const int warp_n = (wid & 1) * 64;    // 0 / 64

    const __half* Ab = g_Ah + (size_t)bm * KDIM;
    const __half* Wb = g_Wh + (size_t)bn * KDIM;

    auto load_stage = [&](int s, int k0) {
        const uint32_t sA = sb + s * ST;
        const uint32_t sB = sA + A_ST;
        #pragma unroll
        for (int j = 0; j < 8; j++) {
            int c   = j * 128 + tid;
            int row = c >> 3, cc = c & 7;
            uint32_t off = (uint32_t)(row * ROWB + cc * 16);
            cpa16(sA + SWZ128(off), Ab + (size_t)row * KDIM + k0 + cc * 8);
        }
        #pragma unroll
        for (int j = 0; j < 8; j++) {
            int c   = j * 128 + tid;
            int row = c >> 3, cc = c & 7;
            uint32_t off = (uint32_t)(row * ROWB + cc * 16);
            cpa16(sB + SWZ128(off), Wb + (size_t)row * KDIM + k0 + cc * 8);
        }
        CP_COMMIT();
    };

    float acc[4][8][4];
    #pragma unroll
    for (int mt = 0; mt < 4; mt++)
        #pragma unroll
        for (int nt = 0; nt < 8; nt++)
            #pragma unroll
            for (int r = 0; r < 4; r++) acc[mt][nt][r] = 0.0f;

    load_stage(0, 0);
    load_stage(1, BK);

    const int NCH = KDIM / BK;            // 64
    const int lr16  = lane & 15;
    const int chalf = (lane >> 4) * 16;   // k-half selector (bytes)

    for (int kc = 0; kc < NCH; kc++) {
        CP_WAIT(STAGES - 2);
        __syncthreads();

        if (kc + STAGES - 1 < NCH)
            load_stage((kc + STAGES - 1) % STAGES, (kc + STAGES - 1) * BK);

        const uint32_t sA = sb + (kc % STAGES) * ST;
        const uint32_t sB = sA + A_ST;

        uint32_t hacc[4][8][2];   // fp16 chunk accumulators

        #pragma unroll
        for (int ks = 0; ks < BK / 16; ks++) {
            const int colb = ks * 32 + chalf;
            uint32_t a[4][4], b[4][4];
            #pragma unroll
            for (int np = 0; np < 4; np++) {
                uint32_t addr = sB + SWZ128((uint32_t)((warp_n + np * 16 + lr16) * ROWB + colb));
                LDSM4(b[np][0], b[np][1], b[np][2], b[np][3], addr);
            }
            #pragma unroll
            for (int mt = 0; mt < 4; mt++) {
                uint32_t addr = sA + SWZ128((uint32_t)((warp_m + mt * 16 + lr16) * ROWB + colb));
                LDSM4(a[mt][0], a[mt][1], a[mt][2], a[mt][3], addr);
            }
            #pragma unroll
            for (int mt = 0; mt < 4; mt++)
                #pragma unroll
                for (int nt = 0; nt < 8; nt++) {
                    uint32_t b0 = b[nt >> 1][nt & 1];
                    uint32_t b1 = b[nt >> 1][2 + (nt & 1)];
                    if (ks == 0)
                        mma_f16h(hacc[mt][nt], a[mt], b0, b1, 0u, 0u);
                    else
                        mma_f16h(hacc[mt][nt], a[mt], b0, b1,
                                 hacc[mt][nt][0], hacc[mt][nt][1]);
                }
        }

        // promote chunk result into fp32 accumulators
        #pragma unroll
        for (int mt = 0; mt < 4; mt++)
            #pragma unroll
            for (int nt = 0; nt < 8; nt++) {
                float2 f0 = __half22float2(*reinterpret_cast<__half2*>(&hacc[mt][nt][0]));
                float2 f1 = __half22float2(*reinterpret_cast<__half2*>(&hacc[mt][nt][1]));
                acc[mt][nt][0] += f0.x;
                acc[mt][nt][1] += f0.y;
                acc[mt][nt][2] += f1.x;
                acc[mt][nt][3] += f1.y;
            }
    }

    // epilogue: fp32 row-major C
    #pragma unroll
    for (int mt = 0; mt < 4; mt++) {
        #pragma unroll
        for (int nt = 0; nt < 8; nt++) {
            int row0 = bm + warp_m + mt * 16 + grp;
            int col0 = bn + warp_n + nt * 8 + tig * 2;
            *reinterpret_cast<float2*>(&C[(size_t)row0 * NDIM + col0]) =
                make_float2(acc[mt][nt][0], acc[mt][nt][1]);
            *reinterpret_cast<float2*>(&C[(size_t)(row0 + 8) * NDIM + col0]) =
                make_float2(acc[mt][nt][2], acc[mt][nt][3]);
        }
    }
}

// ---------------------------------------------------------------------------
// Launch
// ---------------------------------------------------------------------------
extern "C" void kernel_launch(void* const* d_in, const int* in_sizes, int n_in,
                              void* d_out, int out_size) {
    const float* A      = (const float*)d_in[0];
    const int*   wq     = (const int*)d_in[1];
    const float* scales = (const float*)d_in[2];
    float*       C      = (float*)d_out;

    const int M = in_sizes[0] / KDIM;  // 4096

    cudaFuncSetAttribute(gemm_f16_kernel, cudaFuncAttributeMaxDynamicSharedMemorySize,
                         SMEM_BYTES);

    const int a_blocks = (M * KDIM / 8) / 256;
    prep_kernel<<<WQ_BLOCKS + a_blocks, 256>>>(wq, scales, A);

    dim3 grid(NDIM / BN, M / BM);
    gemm_f16_kernel<<<grid, 128, SMEM_BYTES>>>(C, M);
}

// round 16
// speedup vs baseline: 1.1681x; 1.1681x over previous
#include <cuda_runtime.h>
#include <cuda_fp16.h>
#include <cstdint>

// Shapes fixed by setup_inputs: A [4096,4096] f32, w_q [4096,4096] i32, scales [4096,128] f32
static constexpr int KDIM   = 4096;
static constexpr int NDIM   = 4096;
static constexpr int QBLOCK = 32;

// fp16 scratch: A and dequantized W (32 MB each)
__device__ __half g_Ah[(size_t)4096 * KDIM];
__device__ __half g_Wh[(size_t)NDIM * KDIM];

__device__ __forceinline__ uint32_t smem_u32(const void* p) {
    uint32_t a;
    asm("{ .reg .u64 t; cvta.to.shared.u64 t, %1; cvt.u32.u64 %0, t; }" : "=r"(a) : "l"(p));
    return a;
}

__device__ __forceinline__ void cpa16(uint32_t smem_dst, const void* gmem_src) {
    asm volatile("cp.async.cg.shared.global [%0], [%1], 16;"
                 :: "r"(smem_dst), "l"(gmem_src) : "memory");
}
#define CP_COMMIT() asm volatile("cp.async.commit_group;" ::: "memory")
#define CP_WAIT(n)  asm volatile("cp.async.wait_group %0;" :: "n"(n) : "memory")

#define LDSM4(r0, r1, r2, r3, addr)                                            \
    asm volatile("ldmatrix.sync.aligned.m8n8.x4.shared.b16 {%0,%1,%2,%3}, [%4];" \
                 : "=r"(r0), "=r"(r1), "=r"(r2), "=r"(r3) : "r"(addr))

__device__ __forceinline__ void mma_f16(float c[4], const uint32_t a[4],
                                        uint32_t b0, uint32_t b1) {
    asm volatile(
        "mma.sync.aligned.m16n8k16.row.col.f32.f16.f16.f32 "
        "{%0,%1,%2,%3}, {%4,%5,%6,%7}, {%8,%9}, {%0,%1,%2,%3};"
        : "+f"(c[0]), "+f"(c[1]), "+f"(c[2]), "+f"(c[3])
        : "r"(a[0]), "r"(a[1]), "r"(a[2]), "r"(a[3]), "r"(b0), "r"(b1));
}

// ---------------------------------------------------------------------------
// Kernel 1: fused prep. Blocks [0, 8192): dequant w_q -> fp16 W.
//           Blocks [8192, ...): convert A fp32 -> fp16.
// ---------------------------------------------------------------------------
static constexpr int WQ_BLOCKS = (NDIM * KDIM / 8) / 256;  // 8192

__global__ __launch_bounds__(256) void prep_kernel(const int* __restrict__ wq,
                                                   const float* __restrict__ scales,
                                                   const float* __restrict__ A) {
    if (blockIdx.x < WQ_BLOCKS) {
        int idx  = blockIdx.x * 256 + threadIdx.x;   // 8-elem group
        int base = idx << 3;
        int o    = base >> 12;
        int i    = base & (KDIM - 1);
        float s  = scales[o * (KDIM / QBLOCK) + (i >> 5)];
        const int4* wq4 = reinterpret_cast<const int4*>(wq);
        int4 q0 = wq4[idx * 2];
        int4 q1 = wq4[idx * 2 + 1];
        __half2 h[4];
        h[0] = __floats2half2_rn((float)(q0.x - 128) * s, (float)(q0.y - 128) * s);
        h[1] = __floats2half2_rn((float)(q0.z - 128) * s, (float)(q0.w - 128) * s);
        h[2] = __floats2half2_rn((float)(q1.x - 128) * s, (float)(q1.y - 128) * s);
        h[3] = __floats2half2_rn((float)(q1.z - 128) * s, (float)(q1.w - 128) * s);
        reinterpret_cast<uint4*>(g_Wh)[idx] = *reinterpret_cast<uint4*>(h);
    } else {
        int idx = (blockIdx.x - WQ_BLOCKS) * 256 + threadIdx.x;
        const float4* A4 = reinterpret_cast<const float4*>(A);
        float4 v0 = A4[idx * 2];
        float4 v1 = A4[idx * 2 + 1];
        __half2 h[4];
        h[0] = __floats2half2_rn(v0.x, v0.y);
        h[1] = __floats2half2_rn(v0.z, v0.w);
        h[2] = __floats2half2_rn(v1.x, v1.y);
        h[3] = __floats2half2_rn(v1.z, v1.w);
        reinterpret_cast<uint4*>(g_Ah)[idx] = *reinterpret_cast<uint4*>(h);
    }
}

// ---------------------------------------------------------------------------
// Kernel 2: fp16 GEMM (fp32 acc), C = A @ W^T.  CTA 128x128, BK=64, 3-stage
// cp.async.  4 warps as 2(m) x 2(n), warp tile 64x64, 2 CTAs/SM.
// Swizzle folded algebraically: SWZ(row*128 + ks*32 + chalf)
//   = row*128 + (ks*32 ^ chalf ^ (row&7)*16), with (row&7)=(lane&7) warp-
// invariant -> one cs register; every LDSM address is base + (cs ^ const).
// Stage bases rotate through 3 registers (no modulo).
// ---------------------------------------------------------------------------
static constexpr int BM = 128, BN = 128, BK = 64, STAGES = 3;
static constexpr int ROWB  = BK * 2;              // 128 bytes per smem row
static constexpr int A_ST  = BM * ROWB;           // 16 KB
static constexpr int ST    = 2 * A_ST;            // A + B per stage: 32 KB
static constexpr int SMEM_BYTES = STAGES * ST;    // 96 KB

__global__ __launch_bounds__(128, 2) void gemm_f16_kernel(float* __restrict__ C, int M) {
    extern __shared__ char smem[];
    const uint32_t sb = smem_u32(smem);

    const int tid  = threadIdx.x;
    const int wid  = tid >> 5;
    const int lane = tid & 31;
    const int grp  = lane >> 2;
    const int tig  = lane & 3;

    const int bm = blockIdx.y * BM;
    const int bn = blockIdx.x * BN;

    const int warp_m = (wid >> 1) * 64;   // 0 / 64
    const int warp_n = (wid & 1) * 64;    // 0 / 64

    // ---- cp.async precomputed addressing ----
    // thread covers rows trow + 16*j (j=0..7), 8 halves at col tcol*8, both tiles
    const int trow = tid >> 3, tcol = tid & 7;
    const uint32_t ld_off =
        (uint32_t)(trow * ROWB + ((tcol * 16) ^ ((trow & 7) * 16)));  // swizzled, j-invariant
    const __half* agp = g_Ah + (size_t)(bm + trow) * KDIM + tcol * 8;
    const __half* bgp = g_Wh + (size_t)(bn + trow) * KDIM + tcol * 8;

    auto load_stage = [&](uint32_t stb, int k0) {
        const uint32_t sA = stb;
        const uint32_t sB = stb + A_ST;
        #pragma unroll
        for (int j = 0; j < 8; j++)
            cpa16(sA + ld_off + j * (16 * ROWB), agp + (size_t)j * 16 * KDIM + k0);
        #pragma unroll
        for (int j = 0; j < 8; j++)
            cpa16(sB + ld_off + j * (16 * ROWB), bgp + (size_t)j * 16 * KDIM + k0);
        CP_COMMIT();
    };

    // ---- fragment addressing ----
    const int lr16 = lane & 15;
    const uint32_t cs = (uint32_t)((((lane >> 4) * 16) ^ ((lr16 & 7) * 16)));
    uint32_t abase[4], bbase[4];
    #pragma unroll
    for (int mt = 0; mt < 4; mt++) abase[mt] = (uint32_t)((warp_m + mt * 16 + lr16) * ROWB);
    #pragma unroll
    for (int np = 0; np < 4; np++) bbase[np] = (uint32_t)((warp_n + np * 16 + lr16) * ROWB);

    float acc[4][8][4];
    #pragma unroll
    for (int mt = 0; mt < 4; mt++)
        #pragma unroll
        for (int nt = 0; nt < 8; nt++)
            #pragma unroll
            for (int r = 0; r < 4; r++) acc[mt][nt][r] = 0.0f;

    uint32_t st0 = sb, st1 = sb + ST, st2 = sb + 2 * ST;

    load_stage(st0, 0);
    load_stage(st1, BK);

    const int NCH = KDIM / BK;            // 64

    for (int kc = 0; kc < NCH; kc++) {
        CP_WAIT(STAGES - 2);
        __syncthreads();

        if (kc + STAGES - 1 < NCH)
            load_stage(st2, (kc + STAGES - 1) * BK);

        const uint32_t sA = st0;
        const uint32_t sB = st0 + A_ST;

        #pragma unroll
        for (int ks = 0; ks < BK / 16; ks++) {
            const uint32_t kx = cs ^ (uint32_t)(ks * 32);
            uint32_t a[4][4], b[4][4];
            #pragma unroll
            for (int np = 0; np < 4; np++)
                LDSM4(b[np][0], b[np][1], b[np][2], b[np][3], sB + bbase[np] + kx);
            #pragma unroll
            for (int mt = 0; mt < 4; mt++)
                LDSM4(a[mt][0], a[mt][1], a[mt][2], a[mt][3], sA + abase[mt] + kx);
            #pragma unroll
            for (int mt = 0; mt < 4; mt++)
                #pragma unroll
                for (int nt = 0; nt < 8; nt++)
                    mma_f16(acc[mt][nt], a[mt], b[nt >> 1][nt & 1], b[nt >> 1][2 + (nt & 1)]);
        }

        // rotate stages
        uint32_t t = st0; st0 = st1; st1 = st2; st2 = t;
    }

    // epilogue: fp32 row-major C
    #pragma unroll
    for (int mt = 0; mt < 4; mt++) {
        #pragma unroll
        for (int nt = 0; nt < 8; nt++) {
            int row0 = bm + warp_m + mt * 16 + grp;
            int col0 = bn + warp_n + nt * 8 + tig * 2;
            *reinterpret_cast<float2*>(&C[(size_t)row0 * NDIM + col0]) =
                make_float2(acc[mt][nt][0], acc[mt][nt][1]);
            *reinterpret_cast<float2*>(&C[(size_t)(row0 + 8) * NDIM + col0]) =
                make_float2(acc[mt][nt][2], acc[mt][nt][3]);
        }
    }
}

// ---------------------------------------------------------------------------
// Launch
// ---------------------------------------------------------------------------
extern "C" void kernel_launch(void* const* d_in, const int* in_sizes, int n_in,
                              void* d_out, int out_size) {
    const float* A      = (const float*)d_in[0];
    const int*   wq     = (const int*)d_in[1];
    const float* scales = (const float*)d_in[2];
    float*       C      = (float*)d_out;

    const int M = in_sizes[0] / KDIM;  // 4096

    cudaFuncSetAttribute(gemm_f16_kernel, cudaFuncAttributeMaxDynamicSharedMemorySize,
                         SMEM_BYTES);

    const int a_blocks = (M * KDIM / 8) / 256;
    prep_kernel<<<WQ_BLOCKS + a_blocks, 256>>>(wq, scales, A);

    dim3 grid(NDIM / BN, M / BM);
    gemm_f16_kernel<<<grid, 128, SMEM_BYTES>>>(C, M);
}